// round 11
// baseline (speedup 1.0000x reference)
#include <cuda_runtime.h>
#include <cstdint>

#define T_STEPS 1024
#define BATCH   64
#define DIN     256
#define DH      256
#define G4      1024   // 4*DH
#define OUT_MAIN (T_STEPS*BATCH*DH)

// ---------------- scratch (static device globals; no allocation) ----------------
__device__ float g_Gx[(size_t)T_STEPS * BATCH * G4];   // precomputed x-part of gates
__device__ float g_WxT[DIN * G4];                      // Wx transposed [k][j]
__device__ float g_bvec[G4];                           // packed bias
__device__ float g_hT[2][8][DH][8];                    // double-buffered h, transposed [k][batch], tf32
__device__ unsigned int g_flags[8 * 32];               // per-group: 8 producer flags (128B stride)

// ---------------- primitives ----------------
__device__ __forceinline__ void st_release(unsigned int* p, unsigned int v) {
    asm volatile("st.release.gpu.u32 [%0], %1;" :: "l"(p), "r"(v) : "memory");
}
__device__ __forceinline__ uint4 ld_acquire_v4(const unsigned int* p) {
    uint4 v;
    asm volatile("ld.acquire.gpu.global.v4.u32 {%0,%1,%2,%3}, [%4];"
                 : "=r"(v.x), "=r"(v.y), "=r"(v.z), "=r"(v.w) : "l"(p) : "memory");
    return v;
}
__device__ __forceinline__ float4 ldcg4(const float4* p) {
    float4 v;
    asm volatile("ld.global.cg.v4.f32 {%0,%1,%2,%3}, [%4];"
                 : "=f"(v.x), "=f"(v.y), "=f"(v.z), "=f"(v.w) : "l"(p) : "memory");
    return v;
}
__device__ __forceinline__ uint32_t to_tf32(float f) {
    uint32_t r;
    asm("cvt.rna.tf32.f32 %0, %1;" : "=r"(r) : "f"(f));
    return r;
}
__device__ __forceinline__ void mma_tf32(float& d0, float& d1, float& d2, float& d3,
                                         uint32_t a0, uint32_t a1, uint32_t a2, uint32_t a3,
                                         uint32_t b0, uint32_t b1) {
    asm volatile("mma.sync.aligned.m16n8k8.row.col.f32.tf32.tf32.f32 "
                 "{%0,%1,%2,%3}, {%4,%5,%6,%7}, {%8,%9}, {%0,%1,%2,%3};"
                 : "+f"(d0), "+f"(d1), "+f"(d2), "+f"(d3)
                 : "r"(a0), "r"(a1), "r"(a2), "r"(a3), "r"(b0), "r"(b1));
}
__device__ __forceinline__ float sigm(float x) { return 1.f / (1.f + __expf(-x)); }
__device__ __forceinline__ float tanh_fast(float x) {
    float e = __expf(2.f * x);
    return (e - 1.f) * __frcp_rn(e + 1.f);
}

// ---------------- prep: pack Wx (k-major) + bias ----------------
__global__ void prep_kernel(const float* __restrict__ Wf, const float* __restrict__ Wi,
                            const float* __restrict__ Wg, const float* __restrict__ Wo,
                            const float* __restrict__ bF, const float* __restrict__ bI,
                            const float* __restrict__ bG, const float* __restrict__ bO)
{
    int idx = blockIdx.x * blockDim.x + threadIdx.x;
    const float* Ws[4] = {Wf, Wi, Wg, Wo};
    for (int i = idx; i < DIN * G4; i += gridDim.x * blockDim.x) {
        int k = i >> 10;
        int j = i & (G4 - 1);
        int gate = j >> 8;
        int row  = j & 255;
        g_WxT[i] = Ws[gate][row * 512 + k];
    }
    if (idx < G4) {
        int gate = idx >> 8, row = idx & 255;
        const float* bs[4] = {bF, bI, bG, bO};
        g_bvec[idx] = bs[gate][row];
    }
}

// ---------------- init: h0 -> transposed tf32 buffer 0, reset flags ----------------
__global__ void init_kernel(const float* __restrict__ h0)
{
    int i = blockIdx.x * blockDim.x + threadIdx.x;
    if (i < BATCH * DH) {
        int b   = i & 7;
        int k   = (i >> 3) & 255;
        int grp = i >> 11;
        g_hT[0][grp][k][b] = __uint_as_float(to_tf32(h0[(grp * 8 + b) * DH + k]));
    }
    if (i < 8 * 32) g_flags[i] = 0;
}

// ---------------- phase 1: Gx = X @ Wx^T + b   (65536 x 1024 x 256 SGEMM) ----------------
__global__ __launch_bounds__(256) void gemm_x_kernel(const float* __restrict__ A)
{
    __shared__ float As[8][128];
    __shared__ float Bs[8][128];

    int tid = threadIdx.x;
    int bn = blockIdx.x;
    int bm = blockIdx.y;
    int tx = tid & 15;
    int ty = tid >> 4;

    float acc[8][8];
    #pragma unroll
    for (int i = 0; i < 8; i++)
        #pragma unroll
        for (int j = 0; j < 8; j++) acc[i][j] = 0.f;

    const float* Aptr = A + (size_t)bm * 128 * DIN;
    const float* Bptr = g_WxT + bn * 128;

    int arow = tid >> 1;
    int acol = (tid & 1) << 2;
    int bkk  = tid >> 5;
    int bj   = (tid & 31) << 2;

    for (int k0 = 0; k0 < DIN; k0 += 8) {
        float4 a4 = *(const float4*)(Aptr + arow * DIN + k0 + acol);
        As[acol + 0][arow] = a4.x;
        As[acol + 1][arow] = a4.y;
        As[acol + 2][arow] = a4.z;
        As[acol + 3][arow] = a4.w;
        *(float4*)&Bs[bkk][bj] = *(const float4*)(Bptr + (size_t)(k0 + bkk) * G4 + bj);
        __syncthreads();

        #pragma unroll
        for (int kk = 0; kk < 8; kk++) {
            float4 a0 = *(const float4*)&As[kk][ty * 8];
            float4 a1 = *(const float4*)&As[kk][ty * 8 + 4];
            float4 b0 = *(const float4*)&Bs[kk][tx * 8];
            float4 b1 = *(const float4*)&Bs[kk][tx * 8 + 4];
            float af[8] = {a0.x, a0.y, a0.z, a0.w, a1.x, a1.y, a1.z, a1.w};
            float bf[8] = {b0.x, b0.y, b0.z, b0.w, b1.x, b1.y, b1.z, b1.w};
            #pragma unroll
            for (int mi = 0; mi < 8; mi++)
                #pragma unroll
                for (int ni = 0; ni < 8; ni++)
                    acc[mi][ni] += af[mi] * bf[ni];
        }
        __syncthreads();
    }

    int jbase = bn * 128 + tx * 8;
    float4 bb0 = *(const float4*)&g_bvec[jbase];
    float4 bb1 = *(const float4*)&g_bvec[jbase + 4];
    #pragma unroll
    for (int mi = 0; mi < 8; mi++) {
        size_t r = (size_t)bm * 128 + ty * 8 + mi;
        float* op = g_Gx + r * G4 + jbase;
        float4 o0 = make_float4(acc[mi][0] + bb0.x, acc[mi][1] + bb0.y,
                                acc[mi][2] + bb0.z, acc[mi][3] + bb0.w);
        float4 o1 = make_float4(acc[mi][4] + bb1.x, acc[mi][5] + bb1.y,
                                acc[mi][6] + bb1.z, acc[mi][7] + bb1.w);
        *(float4*)op = o0;
        *(float4*)(op + 4) = o1;
    }
}

// ---------------- phase 2: persistent recurrent kernel (tf32 MMA, n=8, in-warp epilogue) ----------------
// 64 CTAs = 8 batch-groups (8 batches) x 8 h-slices (32 h cols x 4 gates = 128 gate rows).
// Warp mt: m-tile of 16 gate rows x 8 batches, k=256 (32 chained m16n8k8, weights in regs).
// Epilogue: 2-round shfl transpose puts all 4 gates of one cell in one lane (32 cells/warp).
// Exchange: L2 flags (8 producers), all-thread v4 acquire polling. 2 barriers/step.
__global__ __launch_bounds__(256, 1) void lstm_kernel(
    const float* __restrict__ Wf, const float* __restrict__ Wi,
    const float* __restrict__ Wg, const float* __restrict__ Wo,
    const float* __restrict__ c0, float* __restrict__ out, int out_size)
{
    __shared__ alignas(16) float4 hT_sm4[DH * 2];   // staged hT: [256 k][8 batch] = 8KB

    int tid  = threadIdx.x;
    int lane = tid & 31;
    int mt   = tid >> 5;          // warp = m-tile 0..7
    int grp  = blockIdx.x >> 3;   // batch group 0..7
    int cg   = blockIdx.x & 7;    // h-slice 0..7

    // ---- load A fragments (weights, tf32) once ----
    int row_off = lane >> 2;            // 0..7 (= 4*q1 + g)
    int colk    = lane & 3;
    int g       = row_off & 3;          // this lane's gate
    int q1      = row_off >> 2;         // 0..1
    const float* Wsel = (g == 0) ? Wf : (g == 1) ? Wi : (g == 2) ? Wg : Wo;
    int hh0 = mt * 4 + q1;              // h col for a0/a2 (rows 0..7)
    int hh1 = hh0 + 2;                  // h col for a1/a3 (rows 8..15)
    const float* p0 = Wsel + (cg * 32 + hh0) * 512 + 256;
    const float* p1 = Wsel + (cg * 32 + hh1) * 512 + 256;

    uint32_t wA[32][4];
    #pragma unroll
    for (int kt = 0; kt < 32; kt++) {
        int k0 = kt * 8;
        wA[kt][0] = to_tf32(p0[k0 + colk]);
        wA[kt][1] = to_tf32(p1[k0 + colk]);
        wA[kt][2] = to_tf32(p0[k0 + colk + 4]);
        wA[kt][3] = to_tf32(p1[k0 + colk + 4]);
    }

    // ---- epilogue cell ownership (post-transpose): every lane owns one cell ----
    int gb0 = g & 1, gb1 = (g >> 1) & 1;
    int c0i = lane & 3;                          // batch pair selector
    int q_own  = q1 + 2 * gb1;                   // 0..3
    int b_own  = 2 * c0i + gb0;                  // 0..7
    int hglob  = cg * 32 + mt * 4 + q_own;
    int bglob  = grp * 8 + b_own;
    float cval = c0[bglob * DH + hglob];

    // ---- B-fragment smem index: k = kt*8 + (lane&3) (+4), n = lane>>2 ----
    int bidx = (lane & 3) * 8 + (lane >> 2);     // word index within [8k][8b] block

    unsigned int* flags = &g_flags[grp * 32];
    const float4* hT_src0 = (const float4*)&g_hT[0][grp][0][0];
    const float4* hT_src1 = (const float4*)&g_hT[1][grp][0][0];
    float* hT_dst0 = &g_hT[0][grp][hglob][b_own];
    float* hT_dst1 = &g_hT[1][grp][hglob][b_own];

    #pragma unroll 1
    for (int t = 0; t < T_STEPS; t++) {
        // prefetch Gx (issued before the wait; DRAM latency hidden)
        const float* gp = g_Gx + (size_t)t * (BATCH * G4) + (size_t)bglob * G4 + hglob;
        float gx0 = __ldcs(gp);
        float gx1 = __ldcs(gp + 256);
        float gx2 = __ldcs(gp + 512);
        float gx3 = __ldcs(gp + 768);

        // all-thread poll: min of 8 producer flags >= t
        for (;;) {
            uint4 f0 = ld_acquire_v4(flags);
            uint4 f1 = ld_acquire_v4(flags + 4);
            unsigned m0 = min(min(f0.x, f0.y), min(f0.z, f0.w));
            unsigned m1 = min(min(f1.x, f1.y), min(f1.z, f1.w));
            if (min(m0, m1) >= (unsigned)t) break;
        }

        // stage hT[t] (256 k x 8 batch = 8KB) into smem; .cg bypasses stale L1
        const float4* hsrc = (t & 1) ? hT_src1 : hT_src0;
        hT_sm4[tid]       = ldcg4(hsrc + tid);
        hT_sm4[tid + 256] = ldcg4(hsrc + tid + 256);
        __syncthreads();

        // tensor MMA: D[16 gate rows x 8 batches] per warp, k=256 in 32 chained steps
        float d0 = 0.f, d1 = 0.f, d2 = 0.f, d3 = 0.f;
        const float* hTf = (const float*)hT_sm4;
        #pragma unroll
        for (int kt = 0; kt < 32; kt++) {
            uint32_t b0 = __float_as_uint(hTf[kt * 64 + bidx]);
            uint32_t b1 = __float_as_uint(hTf[kt * 64 + 32 + bidx]);
            mma_tf32(d0, d1, d2, d3, wA[kt][0], wA[kt][1], wA[kt][2], wA[kt][3], b0, b1);
        }

        // in-warp transpose: 2 butterfly rounds -> lane holds all 4 gates of its cell.
        // d0=(row r_low, b=2c0), d1=(r_low, 2c0+1), d2=(r_low+8, 2c0), d3=(r_low+8, 2c0+1)
        // cells: j0=(q1, even), j1=(q1, odd), j2=(q1+2, even), j3=(q1+2, odd)
        float s0 = gb0 ? d0 : d1;
        float s1 = gb0 ? d2 : d3;
        float r0 = __shfl_xor_sync(0xffffffffu, s0, 4);
        float r1 = __shfl_xor_sync(0xffffffffu, s1, 4);
        float A0 = gb0 ? d1 : d0;      // (gate g,   cell bit1=0)
        float A1 = r0;                 // (gate g^1, cell bit1=0)
        float B0 = gb0 ? d3 : d2;      // (gate g,   cell bit1=1)
        float B1 = r1;                 // (gate g^1, cell bit1=1)
        float t0 = gb1 ? A0 : B0;
        float t1 = gb1 ? A1 : B1;
        float u0 = __shfl_xor_sync(0xffffffffu, t0, 8);   // (gate g^2, own cell)
        float u1 = __shfl_xor_sync(0xffffffffu, t1, 8);   // (gate g^3, own cell)
        float K0 = gb1 ? B0 : A0;      // (gate g,   own cell)
        float K1 = gb1 ? B1 : A1;      // (gate g^1, own cell)
        // absolute gates: f=0, i=1, g=2, o=3
        float vf = gb1 ? (gb0 ? u1 : u0) : (gb0 ? K1 : K0);
        float vi = gb1 ? (gb0 ? u0 : u1) : (gb0 ? K0 : K1);
        float vg = gb1 ? (gb0 ? K1 : K0) : (gb0 ? u1 : u0);
        float vo = gb1 ? (gb0 ? K0 : K1) : (gb0 ? u0 : u1);

        // cell update (every lane owns one cell)
        float fg = sigm(vf + gx0);
        float ig = sigm(vi + gx1);
        float gg = tanh_fast(vg + gx2);
        float og = sigm(vo + gx3);
        cval = fg * cval + ig * gg;
        float hn = og * tanh_fast(cval);

        float hn_tf = __uint_as_float(to_tf32(hn));
        if ((t + 1) & 1) *hT_dst1 = hn_tf; else *hT_dst0 = hn_tf;
        int idx = bglob * DH + hglob;
        out[(size_t)t * (BATCH * DH) + idx] = hn;
        if (t == T_STEPS - 1 && out_size > OUT_MAIN) {
            out[(size_t)OUT_MAIN + idx] = hn;
            out[(size_t)OUT_MAIN + BATCH * DH + idx] = cval;
        }
        __syncthreads();   // all stores done + all smem reads done before release/restage

        // publish h[t+1]
        if (tid == 0) st_release(&flags[cg], (unsigned)(t + 1));
    }
}

// ---------------- launch ----------------
extern "C" void kernel_launch(void* const* d_in, const int* in_sizes, int n_in,
                              void* d_out, int out_size)
{
    const float* inputs = (const float*)d_in[0];
    const float* h0     = (const float*)d_in[1];
    const float* c0     = (const float*)d_in[2];
    const float* Wf     = (const float*)d_in[3];
    const float* bF     = (const float*)d_in[4];
    const float* Wi     = (const float*)d_in[5];
    const float* bI     = (const float*)d_in[6];
    const float* Wg     = (const float*)d_in[7];
    const float* bG     = (const float*)d_in[8];
    const float* Wo     = (const float*)d_in[9];
    const float* bO     = (const float*)d_in[10];
    float* out = (float*)d_out;

    prep_kernel<<<256, 256>>>(Wf, Wi, Wg, Wo, bF, bI, bG, bO);
    init_kernel<<<64, 256>>>(h0);
    gemm_x_kernel<<<dim3(8, 512), 256>>>(inputs);
    lstm_kernel<<<64, 256>>>(Wf, Wi, Wg, Wo, c0, out, out_size);
}

// round 13
// speedup vs baseline: 1.5060x; 1.5060x over previous
#include <cuda_runtime.h>
#include <cstdint>

#define T_STEPS 1024
#define BATCH   64
#define DIN     256
#define DH      256
#define G4      1024   // 4*DH
#define OUT_MAIN (T_STEPS*BATCH*DH)

// ---------------- scratch (static device globals; no allocation) ----------------
__device__ float g_Gx[(size_t)T_STEPS * BATCH * G4];   // precomputed x-part of gates
__device__ float g_Wxp[G4 * DIN];                      // packed Wx rows: [j][k], j = gate*256+h
__device__ float g_bvec[G4];                           // packed bias
__device__ float g_hT[2][16][DH][4];                   // double-buffered h, transposed [k][batch], tf32
__device__ unsigned int g_flags[16 * 16];              // per-group: 8 producer flags

// ---------------- primitives ----------------
__device__ __forceinline__ void st_release(unsigned int* p, unsigned int v) {
    asm volatile("st.release.gpu.u32 [%0], %1;" :: "l"(p), "r"(v) : "memory");
}
__device__ __forceinline__ unsigned int ld_acquire(const unsigned int* p) {
    unsigned int v;
    asm volatile("ld.acquire.gpu.u32 %0, [%1];" : "=r"(v) : "l"(p) : "memory");
    return v;
}
__device__ __forceinline__ float4 ldcg4(const float4* p) {
    float4 v;
    asm volatile("ld.global.cg.v4.f32 {%0,%1,%2,%3}, [%4];"
                 : "=f"(v.x), "=f"(v.y), "=f"(v.z), "=f"(v.w) : "l"(p) : "memory");
    return v;
}
__device__ __forceinline__ uint32_t to_tf32(float f) {
    uint32_t r;
    asm("cvt.rna.tf32.f32 %0, %1;" : "=r"(r) : "f"(f));
    return r;
}
__device__ __forceinline__ void mma_tf32(float& d0, float& d1, float& d2, float& d3,
                                         uint32_t a0, uint32_t a1, uint32_t a2, uint32_t a3,
                                         uint32_t b0, uint32_t b1) {
    asm volatile("mma.sync.aligned.m16n8k8.row.col.f32.tf32.tf32.f32 "
                 "{%0,%1,%2,%3}, {%4,%5,%6,%7}, {%8,%9}, {%0,%1,%2,%3};"
                 : "+f"(d0), "+f"(d1), "+f"(d2), "+f"(d3)
                 : "r"(a0), "r"(a1), "r"(a2), "r"(a3), "r"(b0), "r"(b1));
}
__device__ __forceinline__ float sigm(float x) { return 1.f / (1.f + __expf(-x)); }
__device__ __forceinline__ float tanh_fast(float x) {
    float e = __expf(2.f * x);
    return (e - 1.f) * __frcp_rn(e + 1.f);
}

// ---------------- prep: pack Wx rows (j-major) + bias ----------------
__global__ void prep_kernel(const float* __restrict__ Wf, const float* __restrict__ Wi,
                            const float* __restrict__ Wg, const float* __restrict__ Wo,
                            const float* __restrict__ bF, const float* __restrict__ bI,
                            const float* __restrict__ bG, const float* __restrict__ bO)
{
    int idx = blockIdx.x * blockDim.x + threadIdx.x;
    const float* Ws[4] = {Wf, Wi, Wg, Wo};
    for (int i = idx; i < G4 * DIN; i += gridDim.x * blockDim.x) {
        int j = i >> 8;           // 0..1023
        int k = i & 255;
        g_Wxp[i] = Ws[j >> 8][(j & 255) * 512 + k];   // x-part = first 256 cols
    }
    if (idx < G4) {
        int gate = idx >> 8, row = idx & 255;
        const float* bs[4] = {bF, bI, bG, bO};
        g_bvec[idx] = bs[gate][row];
    }
}

// ---------------- init: h0 -> transposed tf32 buffer 0, reset flags ----------------
__global__ void init_kernel(const float* __restrict__ h0)
{
    int i = blockIdx.x * blockDim.x + threadIdx.x;
    if (i < BATCH * DH) {
        int bb = i >> 8;          // batch 0..63
        int k  = i & 255;         // h index
        g_hT[0][bb >> 2][k][bb & 3] = __uint_as_float(to_tf32(h0[bb * DH + k]));
    }
    if (i < 16 * 16) g_flags[i] = 0;
}

// ---------------- phase 1: Gx = X @ Wx^T + b  -- tf32 tensor-core GEMM ----------------
// M=65536 (rows t*64+b), N=1024 (gate cols), K=256. CTA tile 128x128, 8 warps (32x64 each).
// k staged in 32-wide blocks, tf32-rounded at staging; +4 pad -> conflict-free frag loads.
__global__ __launch_bounds__(256) void gemm_x_kernel(const float* __restrict__ A)
{
    __shared__ float A_sm[128][36];
    __shared__ float B_sm[128][36];

    int tid  = threadIdx.x;
    int lane = tid & 31;
    int wid  = tid >> 5;
    int bn = blockIdx.x;            // 0..7
    int bm = blockIdx.y;            // 0..511
    int wm = (wid & 3) * 32;        // warp m offset in tile
    int wn = (wid >> 2) * 64;       // warp n offset in tile

    float acc[2][8][4];
    #pragma unroll
    for (int mi = 0; mi < 2; mi++)
        #pragma unroll
        for (int ni = 0; ni < 8; ni++)
            #pragma unroll
            for (int q = 0; q < 4; q++) acc[mi][ni][q] = 0.f;

    const float* Aptr = A + (size_t)bm * 128 * DIN;
    const float* Bptr = g_Wxp + (size_t)bn * 128 * DIN;

    int arow = tid >> 1;            // 0..127
    int koff = (tid & 1) * 16;      // half-row

    for (int kb = 0; kb < 8; kb++) {
        int kbase = kb * 32;
        const float4* ap = (const float4*)(Aptr + arow * DIN + kbase + koff);
        const float4* bp = (const float4*)(Bptr + arow * DIN + kbase + koff);
        #pragma unroll
        for (int q = 0; q < 4; q++) {
            float4 av = ap[q];
            float4 bv = bp[q];
            int kk = koff + q * 4;
            A_sm[arow][kk + 0] = __uint_as_float(to_tf32(av.x));
            A_sm[arow][kk + 1] = __uint_as_float(to_tf32(av.y));
            A_sm[arow][kk + 2] = __uint_as_float(to_tf32(av.z));
            A_sm[arow][kk + 3] = __uint_as_float(to_tf32(av.w));
            B_sm[arow][kk + 0] = __uint_as_float(to_tf32(bv.x));
            B_sm[arow][kk + 1] = __uint_as_float(to_tf32(bv.y));
            B_sm[arow][kk + 2] = __uint_as_float(to_tf32(bv.z));
            B_sm[arow][kk + 3] = __uint_as_float(to_tf32(bv.w));
        }
        __syncthreads();

        #pragma unroll
        for (int kc = 0; kc < 32; kc += 8) {
            uint32_t af[2][4];
            #pragma unroll
            for (int mi = 0; mi < 2; mi++) {
                int r = wm + mi * 16 + (lane >> 2);
                af[mi][0] = __float_as_uint(A_sm[r][kc + (lane & 3)]);
                af[mi][1] = __float_as_uint(A_sm[r + 8][kc + (lane & 3)]);
                af[mi][2] = __float_as_uint(A_sm[r][kc + 4 + (lane & 3)]);
                af[mi][3] = __float_as_uint(A_sm[r + 8][kc + 4 + (lane & 3)]);
            }
            #pragma unroll
            for (int ni = 0; ni < 8; ni++) {
                int nr = wn + ni * 8 + (lane >> 2);
                uint32_t b0 = __float_as_uint(B_sm[nr][kc + (lane & 3)]);
                uint32_t b1 = __float_as_uint(B_sm[nr][kc + 4 + (lane & 3)]);
                #pragma unroll
                for (int mi = 0; mi < 2; mi++)
                    mma_tf32(acc[mi][ni][0], acc[mi][ni][1], acc[mi][ni][2], acc[mi][ni][3],
                             af[mi][0], af[mi][1], af[mi][2], af[mi][3], b0, b1);
            }
        }
        __syncthreads();
    }

    // epilogue: c0/c1 at (row = lane>>2, col = 2*(lane&3), +1); c2/c3 at row+8
    int r  = lane >> 2;
    int c2 = 2 * (lane & 3);
    #pragma unroll
    for (int ni = 0; ni < 8; ni++) {
        int j = bn * 128 + wn + ni * 8 + c2;
        float bb0 = g_bvec[j];
        float bb1 = g_bvec[j + 1];
        #pragma unroll
        for (int mi = 0; mi < 2; mi++) {
            size_t m0 = (size_t)bm * 128 + wm + mi * 16 + r;
            float* op  = g_Gx + m0 * G4 + j;
            float* op2 = g_Gx + (m0 + 8) * G4 + j;
            op[0]  = acc[mi][ni][0] + bb0;
            op[1]  = acc[mi][ni][1] + bb1;
            op2[0] = acc[mi][ni][2] + bb0;
            op2[1] = acc[mi][ni][3] + bb1;
        }
    }
}

// ---------------- phase 2: persistent recurrent kernel (tf32 MMA) -- R9, unchanged ----------------
// 128 CTAs = 16 batch-groups (4 batches) x 8 h-slices (32 h cols x 4 gates = 128 gate rows).
// Warp mt: m-tile of 16 gate rows, k=256 in 32 chained m16n8k8 MMAs, weights in registers.
__global__ __launch_bounds__(256, 1) void lstm_kernel(
    const float* __restrict__ Wf, const float* __restrict__ Wi,
    const float* __restrict__ Wg, const float* __restrict__ Wo,
    const float* __restrict__ c0, float* __restrict__ out, int out_size)
{
    __shared__ alignas(16) float4 hT_sm4[DH];     // staged hT: [256 k][4 batch]
    __shared__ float D_sm[128][9];                // gates [gate_row][batch], padded

    int tid  = threadIdx.x;
    int lane = tid & 31;
    int mt   = tid >> 5;          // warp = m-tile 0..7
    int grp  = blockIdx.x >> 3;   // batch group 0..15
    int cg   = blockIdx.x & 7;    // h-slice 0..7

    // ---- load A fragments (weights, tf32) once ----
    int row_off = lane >> 2;
    int colk    = lane & 3;
    int g_th    = row_off & 3;
    const float* Wsel = (g_th == 0) ? Wf : (g_th == 1) ? Wi : (g_th == 2) ? Wg : Wo;
    int hh0 = mt * 4 + (row_off >> 2);
    int hh1 = hh0 + 2;
    const float* p0 = Wsel + (cg * 32 + hh0) * 512 + 256;
    const float* p1 = Wsel + (cg * 32 + hh1) * 512 + 256;

    uint32_t wA[32][4];
    #pragma unroll
    for (int kt = 0; kt < 32; kt++) {
        int k0 = kt * 8;
        wA[kt][0] = to_tf32(p0[k0 + colk]);
        wA[kt][1] = to_tf32(p1[k0 + colk]);
        wA[kt][2] = to_tf32(p0[k0 + colk + 4]);
        wA[kt][3] = to_tf32(p1[k0 + colk + 4]);
    }

    // ---- cell ownership: tid<128, batch = tid&3, h col = tid>>2 ----
    int bloc  = tid & 3;
    int hh    = tid >> 2;
    int bglob = grp * 4 + bloc;
    int hglob = cg * 32 + hh;
    float cval = (tid < 128) ? c0[bglob * DH + hglob] : 0.f;

    // ---- B-fragment smem index (conflict-free) ----
    int bcol  = lane >> 2;
    bool bval = bcol < 4;
    int bidx  = (lane & 3) * 4 + (bval ? bcol : 0);

    unsigned int* flags = &g_flags[grp * 16];
    const float4* hT_src  = (const float4*)&g_hT[0][grp][0][0];
    const float4* hT_src1 = (const float4*)&g_hT[1][grp][0][0];
    float* hT_dst0 = &g_hT[0][grp][hglob][bloc];
    float* hT_dst1 = &g_hT[1][grp][hglob][bloc];

    #pragma unroll 1
    for (int t = 0; t < T_STEPS; t++) {
        // prefetch Gx for this step (independent of flags; hides DRAM latency)
        float gx0, gx1, gx2, gx3;
        if (tid < 128) {
            const float* gp = g_Gx + (size_t)t * (BATCH * G4) + (size_t)bglob * G4 + hglob;
            gx0 = __ldcs(gp);
            gx1 = __ldcs(gp + 256);
            gx2 = __ldcs(gp + 512);
            gx3 = __ldcs(gp + 768);
        }

        // wait for all 8 producers of this group to publish h[t]
        if (tid < 8) {
            while (ld_acquire(&flags[tid]) < (unsigned)t) { }
        }
        __syncthreads();

        // stage hT[t] (256 k x 4 batch) into smem; .cg bypasses stale L1
        hT_sm4[tid] = ldcg4(((t & 1) ? hT_src1 : hT_src) + tid);
        __syncthreads();

        // tensor MMA: D[16 gate rows x 4 batches] per warp, k=256 in 32 chained steps
        float d0 = 0.f, d1 = 0.f, d2 = 0.f, d3 = 0.f;
        const float* hTf = (const float*)hT_sm4;
        #pragma unroll
        for (int kt = 0; kt < 32; kt++) {
            uint32_t b0 = 0u, b1 = 0u;
            if (bval) {
                b0 = __float_as_uint(hTf[kt * 32 + bidx]);
                b1 = __float_as_uint(hTf[kt * 32 + 16 + bidx]);
            }
            mma_tf32(d0, d1, d2, d3, wA[kt][0], wA[kt][1], wA[kt][2], wA[kt][3], b0, b1);
        }

        // write D cols 0..3 (batches) to smem
        int r0 = mt * 16 + (lane >> 2);
        int cc = lane & 3;
        if (cc < 2) {
            D_sm[r0][2 * cc]         = d0;
            D_sm[r0][2 * cc + 1]     = d1;
            D_sm[r0 + 8][2 * cc]     = d2;
            D_sm[r0 + 8][2 * cc + 1] = d3;
        }
        __syncthreads();

        // cell update: thread (hh, bloc); gates at rows hh*4+g
        if (tid < 128) {
            float fg = sigm(D_sm[hh * 4 + 0][bloc] + gx0);
            float ig = sigm(D_sm[hh * 4 + 1][bloc] + gx1);
            float gg = tanh_fast(D_sm[hh * 4 + 2][bloc] + gx2);
            float og = sigm(D_sm[hh * 4 + 3][bloc] + gx3);
            cval = fg * cval + ig * gg;
            float hn = og * tanh_fast(cval);
            float hn_tf = __uint_as_float(to_tf32(hn));
            if ((t + 1) & 1) *hT_dst1 = hn_tf; else *hT_dst0 = hn_tf;
            int idx = bglob * DH + hglob;
            out[(size_t)t * (BATCH * DH) + idx] = hn;
            if (t == T_STEPS - 1 && out_size > OUT_MAIN) {
                out[(size_t)OUT_MAIN + idx] = hn;
                out[(size_t)OUT_MAIN + BATCH * DH + idx] = cval;
            }
        }
        __syncthreads();

        // publish: all this CTA's hT stores ordered before the flag (bar + release)
        if (tid == 0) st_release(&flags[cg], (unsigned)(t + 1));
    }
}

// ---------------- launch ----------------
extern "C" void kernel_launch(void* const* d_in, const int* in_sizes, int n_in,
                              void* d_out, int out_size)
{
    const float* inputs = (const float*)d_in[0];
    const float* h0     = (const float*)d_in[1];
    const float* c0     = (const float*)d_in[2];
    const float* Wf     = (const float*)d_in[3];
    const float* bF     = (const float*)d_in[4];
    const float* Wi     = (const float*)d_in[5];
    const float* bI     = (const float*)d_in[6];
    const float* Wg     = (const float*)d_in[7];
    const float* bG     = (const float*)d_in[8];
    const float* Wo     = (const float*)d_in[9];
    const float* bO     = (const float*)d_in[10];
    float* out = (float*)d_out;

    prep_kernel<<<256, 256>>>(Wf, Wi, Wg, Wo, bF, bI, bG, bO);
    init_kernel<<<64, 256>>>(h0);
    gemm_x_kernel<<<dim3(8, 512), 256>>>(inputs);
    lstm_kernel<<<128, 256>>>(Wf, Wi, Wg, Wo, c0, out, out_size);
}